// round 1
// baseline (speedup 1.0000x reference)
#include <cuda_runtime.h>
#include <math.h>

#define CN 64
#define IN_N 64
#define RN 36
#define LN 40
#define DN 1024
#define SN 256
#define DC 128
#define NCH (DN/DC)
#define SP 132   // padded smem row stride (floats) for img/cap/sim

// shared memory layout (floats)
#define OFF_W    0
#define OFF_IMG  (OFF_W + DC*SN)        // 32768
#define OFF_CAP  (OFF_IMG + RN*SP)
#define OFF_SIM  (OFF_CAP + LN*SP)
#define OFF_ATTN (OFF_SIM + LN*SP)
#define OFF_AT   (OFF_ATTN + RN*41)
#define OFF_INVN (OFF_AT + LN*40)
#define OFF_B    (OFF_INVN + LN)
#define SMEM_FLOATS (OFF_B + SN)

__device__ __forceinline__ float warp_sum(float v) {
    #pragma unroll
    for (int o = 16; o > 0; o >>= 1) v += __shfl_xor_sync(0xffffffffu, v, o);
    return v;
}

__global__ __launch_bounds__(256, 1)
void graphembt_kernel(const float* __restrict__ img_g,
                      const float* __restrict__ cap_g,
                      const int*   __restrict__ lens_g,
                      const float* __restrict__ W_g,
                      const float* __restrict__ b_g,
                      float*       __restrict__ out_g)
{
    extern __shared__ float sm[];
    float* sW   = sm + OFF_W;
    float* sImg = sm + OFF_IMG;
    float* sCap = sm + OFF_CAP;
    float* sSim = sm + OFF_SIM;
    float* sAttn= sm + OFF_ATTN;
    float* sAT  = sm + OFF_AT;
    float* sInv = sm + OFF_INVN;
    float* sB   = sm + OFF_B;

    const int i    = blockIdx.x;   // image
    const int c    = blockIdx.y;   // caption
    const int tid  = threadIdx.x;
    const int w    = tid >> 5;     // warp 0..7
    const int lane = tid & 31;

    const float* imgB = img_g + (size_t)i * (RN * DN);
    const float* capB = cap_g + (size_t)c * (LN * DN);

    if (tid < SN/4)
        *(float4*)(sB + tid*4) = *(const float4*)(b_g + tid*4);

    // ======== Phase 1: attn[r][l] = img[i,r,:] . cap[c,l,:] ========
    float p1[4][4];
    #pragma unroll
    for (int a = 0; a < 4; a++)
        #pragma unroll
        for (int b = 0; b < 4; b++) p1[a][b] = 0.f;

    const int rt = tid / 10;         // valid for tid < 90
    const int lt = tid - rt * 10;

    for (int k = 0; k < NCH; k++) {
        __syncthreads();
        for (int idx = tid; idx < RN*(DC/4); idx += 256) {
            int r = idx >> 5, dq = idx & 31;
            *(float4*)(sImg + r*SP + dq*4) =
                *(const float4*)(imgB + r*DN + k*DC + dq*4);
        }
        for (int idx = tid; idx < LN*(DC/4); idx += 256) {
            int l = idx >> 5, dq = idx & 31;
            *(float4*)(sCap + l*SP + dq*4) =
                *(const float4*)(capB + l*DN + k*DC + dq*4);
        }
        __syncthreads();
        if (tid < 90) {
            #pragma unroll 2
            for (int d = 0; d < DC; d++) {
                float av[4], bv[4];
                #pragma unroll
                for (int a = 0; a < 4; a++) av[a] = sImg[(4*rt+a)*SP + d];
                #pragma unroll
                for (int b = 0; b < 4; b++) bv[b] = sCap[(4*lt+b)*SP + d];
                #pragma unroll
                for (int a = 0; a < 4; a++)
                    #pragma unroll
                    for (int b = 0; b < 4; b++)
                        p1[a][b] = fmaf(av[a], bv[b], p1[a][b]);
            }
        }
    }
    __syncthreads();
    if (tid < 90) {
        #pragma unroll
        for (int a = 0; a < 4; a++)
            #pragma unroll
            for (int b = 0; b < 4; b++)
                sAttn[(4*rt+a)*41 + (4*lt+b)] = p1[a][b];
    }
    __syncthreads();

    // ======== Phase 2a: leaky relu + l2norm over l (per r) ========
    if (tid < RN) {
        float ss = 0.f;
        #pragma unroll 4
        for (int l = 0; l < LN; l++) {
            float x = sAttn[tid*41 + l];
            x = (x > 0.f) ? x : 0.1f * x;
            sAttn[tid*41 + l] = x;
            ss = fmaf(x, x, ss);
        }
        float inv = 1.f / (sqrtf(ss) + 1e-8f);
        #pragma unroll 4
        for (int l = 0; l < LN; l++) sAttn[tid*41 + l] *= inv;
    }
    __syncthreads();

    // ======== Phase 2b: softmax over r (per l) -> sAT[l][r] ========
    if (tid < LN) {
        float mx = -1e30f;
        #pragma unroll 4
        for (int r = 0; r < RN; r++)
            mx = fmaxf(mx, sAttn[r*41 + tid] * 9.0f);
        float sum = 0.f;
        #pragma unroll 4
        for (int r = 0; r < RN; r++) {
            float e = expf(sAttn[r*41 + tid] * 9.0f - mx);
            sAT[tid*40 + r] = e;
            sum += e;
        }
        float inv = 1.f / sum;
        #pragma unroll 4
        for (int r = 0; r < RN; r++) sAT[tid*40 + r] *= inv;
    }

    // ======== Phase 3a: wc sum-of-squares (pass 1 over D) ========
    // warp w owns l in {5w..5w+4}; lane owns d quad [lane*4, lane*4+4)
    float ssq[5] = {0.f, 0.f, 0.f, 0.f, 0.f};
    for (int k = 0; k < NCH; k++) {
        __syncthreads();
        for (int idx = tid; idx < RN*(DC/4); idx += 256) {
            int r = idx >> 5, dq = idx & 31;
            *(float4*)(sImg + r*SP + dq*4) =
                *(const float4*)(imgB + r*DN + k*DC + dq*4);
        }
        __syncthreads();
        float wcv[5][4];
        #pragma unroll
        for (int ii = 0; ii < 5; ii++)
            #pragma unroll
            for (int j = 0; j < 4; j++) wcv[ii][j] = 0.f;
        for (int r = 0; r < RN; r++) {
            float4 im = *(const float4*)(sImg + r*SP + lane*4);
            #pragma unroll
            for (int ii = 0; ii < 5; ii++) {
                float a = sAT[(5*w+ii)*40 + r];
                wcv[ii][0] = fmaf(a, im.x, wcv[ii][0]);
                wcv[ii][1] = fmaf(a, im.y, wcv[ii][1]);
                wcv[ii][2] = fmaf(a, im.z, wcv[ii][2]);
                wcv[ii][3] = fmaf(a, im.w, wcv[ii][3]);
            }
        }
        #pragma unroll
        for (int ii = 0; ii < 5; ii++)
            ssq[ii] += wcv[ii][0]*wcv[ii][0] + wcv[ii][1]*wcv[ii][1]
                     + wcv[ii][2]*wcv[ii][2] + wcv[ii][3]*wcv[ii][3];
    }
    #pragma unroll
    for (int ii = 0; ii < 5; ii++) {
        float s = warp_sum(ssq[ii]);
        if (lane == 0) sInv[5*w+ii] = 1.f / (sqrtf(s) + 1e-8f);
    }

    // ======== Phase 3b: wc -> sim -> GEMM sim @ W (pass 2 over D) ========
    float acc[5][8];
    #pragma unroll
    for (int kk = 0; kk < 5; kk++)
        #pragma unroll
        for (int j = 0; j < 8; j++) acc[kk][j] = 0.f;

    for (int k = 0; k < NCH; k++) {
        __syncthreads();
        for (int idx = tid; idx < RN*(DC/4); idx += 256) {
            int r = idx >> 5, dq = idx & 31;
            *(float4*)(sImg + r*SP + dq*4) =
                *(const float4*)(imgB + r*DN + k*DC + dq*4);
        }
        for (int idx = tid; idx < LN*(DC/4); idx += 256) {
            int l = idx >> 5, dq = idx & 31;
            *(float4*)(sCap + l*SP + dq*4) =
                *(const float4*)(capB + l*DN + k*DC + dq*4);
        }
        for (int idx = tid; idx < DC*(SN/4); idx += 256) {
            int d = idx >> 6, sq = idx & 63;
            *(float4*)(sW + d*SN + sq*4) =
                *(const float4*)(W_g + (size_t)(k*DC + d)*SN + sq*4);
        }
        __syncthreads();

        float wcv[5][4];
        #pragma unroll
        for (int ii = 0; ii < 5; ii++)
            #pragma unroll
            for (int j = 0; j < 4; j++) wcv[ii][j] = 0.f;
        for (int r = 0; r < RN; r++) {
            float4 im = *(const float4*)(sImg + r*SP + lane*4);
            #pragma unroll
            for (int ii = 0; ii < 5; ii++) {
                float a = sAT[(5*w+ii)*40 + r];
                wcv[ii][0] = fmaf(a, im.x, wcv[ii][0]);
                wcv[ii][1] = fmaf(a, im.y, wcv[ii][1]);
                wcv[ii][2] = fmaf(a, im.z, wcv[ii][2]);
                wcv[ii][3] = fmaf(a, im.w, wcv[ii][3]);
            }
        }
        #pragma unroll
        for (int ii = 0; ii < 5; ii++) {
            float inv = sInv[5*w+ii];
            float4 cp = *(const float4*)(sCap + (5*w+ii)*SP + lane*4);
            float v0 = fmaf(wcv[ii][0], inv, -cp.x);
            float v1 = fmaf(wcv[ii][1], inv, -cp.y);
            float v2 = fmaf(wcv[ii][2], inv, -cp.z);
            float v3 = fmaf(wcv[ii][3], inv, -cp.w);
            float4 sv = make_float4(v0*v0, v1*v1, v2*v2, v3*v3);
            *(float4*)(sSim + (5*w+ii)*SP + lane*4) = sv;
        }
        __syncthreads();

        // GEMM: warp w -> l = w + 8*kk ; lane -> s = lane + 32*j
        #pragma unroll 2
        for (int d = 0; d < DC; d++) {
            float sv[5];
            #pragma unroll
            for (int kk = 0; kk < 5; kk++)
                sv[kk] = sSim[(w + 8*kk)*SP + d];
            #pragma unroll
            for (int j = 0; j < 8; j++) {
                float wv = sW[d*SN + lane + 32*j];
                #pragma unroll
                for (int kk = 0; kk < 5; kk++)
                    acc[kk][j] = fmaf(sv[kk], wv, acc[kk][j]);
            }
        }
    }

    // ======== Epilogue: +b, relu, l2norm over s, mask, store ========
    const int clen = lens_g[c];
    float* outB = out_g + (size_t)(c*IN_N + i) * (LN*SN);
    #pragma unroll
    for (int kk = 0; kk < 5; kk++) {
        const int l = w + 8*kk;
        float vs[8]; float ss = 0.f;
        #pragma unroll
        for (int j = 0; j < 8; j++) {
            float v = acc[kk][j] + sB[lane + 32*j];
            v = fmaxf(v, 0.f);
            vs[j] = v;
            ss = fmaf(v, v, ss);
        }
        ss = warp_sum(ss);
        float inv = 1.f / (sqrtf(ss) + 1e-8f);
        if (l >= clen) inv = 0.f;
        #pragma unroll
        for (int j = 0; j < 8; j++)
            outB[(size_t)l*SN + lane + 32*j] = vs[j] * inv;
    }
}

extern "C" void kernel_launch(void* const* d_in, const int* in_sizes, int n_in,
                              void* d_out, int out_size)
{
    const float* img  = (const float*)d_in[0];
    const float* cap  = (const float*)d_in[1];
    const int*   lens = (const int*)  d_in[2];
    // d_in[3] = adjs, d_in[4] = depends : unused by the reference math
    const float* W    = (const float*)d_in[5];
    const float* b    = (const float*)d_in[6];
    float* out = (float*)d_out;
    (void)in_sizes; (void)n_in; (void)out_size;

    cudaFuncSetAttribute(graphembt_kernel,
                         cudaFuncAttributeMaxDynamicSharedMemorySize,
                         SMEM_FLOATS * sizeof(float));

    dim3 grid(IN_N, CN);
    graphembt_kernel<<<grid, 256, SMEM_FLOATS * sizeof(float)>>>(
        img, cap, lens, W, b, out);
}

// round 2
// speedup vs baseline: 1.1131x; 1.1131x over previous
#include <cuda_runtime.h>
#include <math.h>

#define CN 64
#define IN_N 64
#define RN 36
#define LN 40
#define DN 1024
#define SN 256
#define DC 128
#define NCH (DN/DC)
#define SP 132
#define NT 512

// shared memory layout (floats) -- all offsets multiples of 4 (16B aligned)
#define OFF_W    0
#define OFF_IMG  (OFF_W + DC*SN)              // 32768
#define OFF_CAP  (OFF_IMG + RN*SP)            // +4752
#define OFF_SIM  (OFF_CAP + LN*SP)            // +5280
#define OFF_ATTN (OFF_SIM + LN*SP)            // +5280
#define OFF_AT   (OFF_ATTN + RN*41)           // +1476
#define OFF_INVN (OFF_AT + LN*40)             // +1600
#define OFF_RED  (OFF_INVN + LN)              // +40
#define OFF_B    (OFF_RED + LN*2)             // +80
#define SMEM_FLOATS (OFF_B + SN)

__device__ __forceinline__ float warp_sum(float v) {
    #pragma unroll
    for (int o = 16; o > 0; o >>= 1) v += __shfl_xor_sync(0xffffffffu, v, o);
    return v;
}

__global__ __launch_bounds__(NT, 1)
void graphembt_kernel(const float* __restrict__ img_g,
                      const float* __restrict__ cap_g,
                      const int*   __restrict__ lens_g,
                      const float* __restrict__ W_g,
                      const float* __restrict__ b_g,
                      float*       __restrict__ out_g)
{
    extern __shared__ float sm[];
    float* sW   = sm + OFF_W;
    float* sImg = sm + OFF_IMG;
    float* sCap = sm + OFF_CAP;
    float* sSim = sm + OFF_SIM;
    float* sAttn= sm + OFF_ATTN;
    float* sAT  = sm + OFF_AT;
    float* sInv = sm + OFF_INVN;
    float* sRed = sm + OFF_RED;
    float* sB   = sm + OFF_B;

    const int i    = blockIdx.x;
    const int c    = blockIdx.y;
    const int tid  = threadIdx.x;
    const int w    = tid >> 5;
    const int lane = tid & 31;
    const int g    = w & 7;    // l-group: rows 5g..5g+4
    const int h    = w >> 3;   // d/s half

    const float* imgB = img_g + (size_t)i * (RN * DN);
    const float* capB = cap_g + (size_t)c * (LN * DN);

    if (tid < SN/4)
        *(float4*)(sB + tid*4) = *(const float4*)(b_g + tid*4);

    // ======== Phase 1: attn[r][l] = img[i,r,:] . cap[c,l,:] ========
    // 180 threads, each a 2r x 4l tile, float4 over d
    const int rg = tid / 10;          // 0..17 (tid<180)
    const int lg = tid - rg * 10;     // 0..9
    const int r0 = 2 * rg, l0 = 4 * lg;
    float p1[2][4];
    #pragma unroll
    for (int a = 0; a < 2; a++)
        #pragma unroll
        for (int b = 0; b < 4; b++) p1[a][b] = 0.f;

    for (int k = 0; k < NCH; k++) {
        __syncthreads();
        for (int idx = tid; idx < RN*(DC/4); idx += NT) {
            int r = idx >> 5, dq = idx & 31;
            *(float4*)(sImg + r*SP + dq*4) =
                *(const float4*)(imgB + r*DN + k*DC + dq*4);
        }
        for (int idx = tid; idx < LN*(DC/4); idx += NT) {
            int l = idx >> 5, dq = idx & 31;
            *(float4*)(sCap + l*SP + dq*4) =
                *(const float4*)(capB + l*DN + k*DC + dq*4);
        }
        __syncthreads();
        if (tid < 180) {
            #pragma unroll 2
            for (int d4 = 0; d4 < DC/4; d4++) {
                float4 av[2], cv[4];
                #pragma unroll
                for (int a = 0; a < 2; a++)
                    av[a] = *(float4*)(sImg + (r0+a)*SP + d4*4);
                #pragma unroll
                for (int b = 0; b < 4; b++)
                    cv[b] = *(float4*)(sCap + (l0+b)*SP + d4*4);
                #pragma unroll
                for (int a = 0; a < 2; a++)
                    #pragma unroll
                    for (int b = 0; b < 4; b++) {
                        p1[a][b] = fmaf(av[a].x, cv[b].x, p1[a][b]);
                        p1[a][b] = fmaf(av[a].y, cv[b].y, p1[a][b]);
                        p1[a][b] = fmaf(av[a].z, cv[b].z, p1[a][b]);
                        p1[a][b] = fmaf(av[a].w, cv[b].w, p1[a][b]);
                    }
            }
        }
    }
    __syncthreads();
    if (tid < 180) {
        #pragma unroll
        for (int a = 0; a < 2; a++)
            #pragma unroll
            for (int b = 0; b < 4; b++)
                sAttn[(r0+a)*41 + (l0+b)] = p1[a][b];
    }
    __syncthreads();

    // ======== Phase 2a: leaky relu + l2norm over l (per r) ========
    if (tid < RN) {
        float ss = 0.f;
        #pragma unroll 4
        for (int l = 0; l < LN; l++) {
            float x = sAttn[tid*41 + l];
            x = (x > 0.f) ? x : 0.1f * x;
            sAttn[tid*41 + l] = x;
            ss = fmaf(x, x, ss);
        }
        float inv = 1.f / (sqrtf(ss) + 1e-8f);
        #pragma unroll 4
        for (int l = 0; l < LN; l++) sAttn[tid*41 + l] *= inv;
    }
    __syncthreads();

    // ======== Phase 2b: softmax over r (per l) -> sAT[l][r] ========
    if (tid < LN) {
        float mx = -1e30f;
        #pragma unroll 4
        for (int r = 0; r < RN; r++)
            mx = fmaxf(mx, sAttn[r*41 + tid] * 9.0f);
        float sum = 0.f;
        #pragma unroll 4
        for (int r = 0; r < RN; r++) {
            float e = expf(sAttn[r*41 + tid] * 9.0f - mx);
            sAT[tid*40 + r] = e;
            sum += e;
        }
        float inv = 1.f / sum;
        #pragma unroll 4
        for (int r = 0; r < RN; r++) sAT[tid*40 + r] *= inv;
    }

    // ======== Phase 3a: wc sum-of-squares (pass 1 over D) ========
    // warp (g,h): l rows 5g..5g+4 ; lane owns d = h*64 + lane*2 (float2)
    const int dlo = h*64 + lane*2;
    float ssq[5] = {0.f,0.f,0.f,0.f,0.f};
    for (int k = 0; k < NCH; k++) {
        __syncthreads();
        for (int idx = tid; idx < RN*(DC/4); idx += NT) {
            int r = idx >> 5, dq = idx & 31;
            *(float4*)(sImg + r*SP + dq*4) =
                *(const float4*)(imgB + r*DN + k*DC + dq*4);
        }
        __syncthreads();
        float wcx[5], wcy[5];
        #pragma unroll
        for (int ii = 0; ii < 5; ii++) { wcx[ii]=0.f; wcy[ii]=0.f; }
        #pragma unroll 3
        for (int r = 0; r < RN; r += 4) {
            float2 im[4];
            #pragma unroll
            for (int q = 0; q < 4; q++)
                im[q] = *(float2*)(sImg + (r+q)*SP + dlo);
            #pragma unroll
            for (int ii = 0; ii < 5; ii++) {
                float4 a4 = *(float4*)(sAT + (5*g+ii)*40 + r);
                wcx[ii] = fmaf(a4.x, im[0].x, wcx[ii]);
                wcy[ii] = fmaf(a4.x, im[0].y, wcy[ii]);
                wcx[ii] = fmaf(a4.y, im[1].x, wcx[ii]);
                wcy[ii] = fmaf(a4.y, im[1].y, wcy[ii]);
                wcx[ii] = fmaf(a4.z, im[2].x, wcx[ii]);
                wcy[ii] = fmaf(a4.z, im[2].y, wcy[ii]);
                wcx[ii] = fmaf(a4.w, im[3].x, wcx[ii]);
                wcy[ii] = fmaf(a4.w, im[3].y, wcy[ii]);
            }
        }
        #pragma unroll
        for (int ii = 0; ii < 5; ii++)
            ssq[ii] += wcx[ii]*wcx[ii] + wcy[ii]*wcy[ii];
    }
    #pragma unroll
    for (int ii = 0; ii < 5; ii++) {
        float s = warp_sum(ssq[ii]);
        if (lane == 0) sRed[(5*g+ii)*2 + h] = s;
    }
    __syncthreads();
    if (tid < LN)
        sInv[tid] = 1.f / (sqrtf(sRed[tid*2] + sRed[tid*2+1]) + 1e-8f);

    // ======== Phase 3b: wc -> sim -> GEMM sim @ W ========
    // GEMM: warp (g,h): l = 5g+kk ; s = 128h + lane*4 .. +3
    const int s0 = h*128 + lane*4;
    float acc[5][4];
    #pragma unroll
    for (int kk = 0; kk < 5; kk++)
        #pragma unroll
        for (int j = 0; j < 4; j++) acc[kk][j] = 0.f;

    for (int k = 0; k < NCH; k++) {
        __syncthreads();
        for (int idx = tid; idx < RN*(DC/4); idx += NT) {
            int r = idx >> 5, dq = idx & 31;
            *(float4*)(sImg + r*SP + dq*4) =
                *(const float4*)(imgB + r*DN + k*DC + dq*4);
        }
        for (int idx = tid; idx < LN*(DC/4); idx += NT) {
            int l = idx >> 5, dq = idx & 31;
            *(float4*)(sCap + l*SP + dq*4) =
                *(const float4*)(capB + l*DN + k*DC + dq*4);
        }
        for (int idx = tid; idx < DC*(SN/4); idx += NT) {
            int d = idx >> 6, sq = idx & 63;
            *(float4*)(sW + d*SN + sq*4) =
                *(const float4*)(W_g + (size_t)(k*DC + d)*SN + sq*4);
        }
        __syncthreads();

        // wc recompute for this chunk
        float wcx[5], wcy[5];
        #pragma unroll
        for (int ii = 0; ii < 5; ii++) { wcx[ii]=0.f; wcy[ii]=0.f; }
        #pragma unroll 3
        for (int r = 0; r < RN; r += 4) {
            float2 im[4];
            #pragma unroll
            for (int q = 0; q < 4; q++)
                im[q] = *(float2*)(sImg + (r+q)*SP + dlo);
            #pragma unroll
            for (int ii = 0; ii < 5; ii++) {
                float4 a4 = *(float4*)(sAT + (5*g+ii)*40 + r);
                wcx[ii] = fmaf(a4.x, im[0].x, wcx[ii]);
                wcy[ii] = fmaf(a4.x, im[0].y, wcy[ii]);
                wcx[ii] = fmaf(a4.y, im[1].x, wcx[ii]);
                wcy[ii] = fmaf(a4.y, im[1].y, wcy[ii]);
                wcx[ii] = fmaf(a4.z, im[2].x, wcx[ii]);
                wcy[ii] = fmaf(a4.z, im[2].y, wcy[ii]);
                wcx[ii] = fmaf(a4.w, im[3].x, wcx[ii]);
                wcy[ii] = fmaf(a4.w, im[3].y, wcy[ii]);
            }
        }
        #pragma unroll
        for (int ii = 0; ii < 5; ii++) {
            float inv = sInv[5*g+ii];
            float2 cp = *(float2*)(sCap + (5*g+ii)*SP + dlo);
            float v0 = fmaf(wcx[ii], inv, -cp.x);
            float v1 = fmaf(wcy[ii], inv, -cp.y);
            float2 sv; sv.x = v0*v0; sv.y = v1*v1;
            *(float2*)(sSim + (5*g+ii)*SP + dlo) = sv;
        }
        __syncthreads();

        // GEMM over this chunk, 4 d at a time
        #pragma unroll 2
        for (int d = 0; d < DC; d += 4) {
            float4 sv[5];
            #pragma unroll
            for (int kk = 0; kk < 5; kk++)
                sv[kk] = *(float4*)(sSim + (5*g+kk)*SP + d);
            #pragma unroll
            for (int dd = 0; dd < 4; dd++) {
                float4 wv = *(float4*)(sW + (d+dd)*SN + s0);
                #pragma unroll
                for (int kk = 0; kk < 5; kk++) {
                    float s = (dd==0) ? sv[kk].x : (dd==1) ? sv[kk].y
                            : (dd==2) ? sv[kk].z : sv[kk].w;
                    acc[kk][0] = fmaf(s, wv.x, acc[kk][0]);
                    acc[kk][1] = fmaf(s, wv.y, acc[kk][1]);
                    acc[kk][2] = fmaf(s, wv.z, acc[kk][2]);
                    acc[kk][3] = fmaf(s, wv.w, acc[kk][3]);
                }
            }
        }
    }

    // ======== Epilogue: +b, relu, l2norm over s (split halves), mask ========
    const int clen = lens_g[c];
    float vs[5][4];
    #pragma unroll
    for (int kk = 0; kk < 5; kk++) {
        float pss = 0.f;
        #pragma unroll
        for (int j = 0; j < 4; j++) {
            float v = acc[kk][j] + sB[s0 + j];
            v = fmaxf(v, 0.f);
            vs[kk][j] = v;
            pss = fmaf(v, v, pss);
        }
        pss = warp_sum(pss);
        if (lane == 0) sRed[(5*g+kk)*2 + h] = pss;
    }
    __syncthreads();
    if (tid < LN) {
        float ss = sRed[tid*2] + sRed[tid*2+1];
        float inv = 1.f / (sqrtf(ss) + 1e-8f);
        sInv[tid] = (tid < clen) ? inv : 0.f;
    }
    __syncthreads();

    float* outB = out_g + (size_t)(c*IN_N + i) * (LN*SN);
    #pragma unroll
    for (int kk = 0; kk < 5; kk++) {
        const int l = 5*g + kk;
        float inv = sInv[l];
        float4 o;
        o.x = vs[kk][0]*inv; o.y = vs[kk][1]*inv;
        o.z = vs[kk][2]*inv; o.w = vs[kk][3]*inv;
        *(float4*)(outB + (size_t)l*SN + s0) = o;
    }
}

extern "C" void kernel_launch(void* const* d_in, const int* in_sizes, int n_in,
                              void* d_out, int out_size)
{
    const float* img  = (const float*)d_in[0];
    const float* cap  = (const float*)d_in[1];
    const int*   lens = (const int*)  d_in[2];
    const float* W    = (const float*)d_in[5];
    const float* b    = (const float*)d_in[6];
    float* out = (float*)d_out;
    (void)in_sizes; (void)n_in; (void)out_size;

    cudaFuncSetAttribute(graphembt_kernel,
                         cudaFuncAttributeMaxDynamicSharedMemorySize,
                         SMEM_FLOATS * sizeof(float));

    dim3 grid(IN_N, CN);
    graphembt_kernel<<<grid, NT, SMEM_FLOATS * sizeof(float)>>>(
        img, cap, lens, W, b, out);
}

// round 3
// speedup vs baseline: 1.1144x; 1.0012x over previous
#include <cuda_runtime.h>
#include <math.h>

#define CN 64
#define IN_N 64
#define RN 36
#define LN 40
#define DN 1024
#define SN 256
#define DC 128
#define NCH (DN/DC)
#define SP 132
#define NT 512

// shared memory layout (floats) -- all offsets multiples of 4 (16B aligned)
#define OFF_W    0
#define OFF_IMG  (OFF_W + DC*SN)              // 32768
#define OFF_CAP  (OFF_IMG + RN*SP)            // +4752
#define OFF_SIM  (OFF_CAP + LN*SP)            // +5280
#define OFF_ATTN (OFF_SIM + LN*SP)            // +5280
#define OFF_AT   (OFF_ATTN + RN*41)           // +1476
#define OFF_INVN (OFF_AT + LN*40)             // +1600
#define OFF_RED  (OFF_INVN + LN)              // +40
#define OFF_B    (OFF_RED + LN*2)             // +80
#define SMEM_FLOATS (OFF_B + SN)

__device__ __forceinline__ float warp_sum(float v) {
    #pragma unroll
    for (int o = 16; o > 0; o >>= 1) v += __shfl_xor_sync(0xffffffffu, v, o);
    return v;
}

__global__ __launch_bounds__(NT, 1)
void graphembt_kernel(const float* __restrict__ img_g,
                      const float* __restrict__ cap_g,
                      const int*   __restrict__ lens_g,
                      const float* __restrict__ W_g,
                      const float* __restrict__ b_g,
                      float*       __restrict__ out_g)
{
    extern __shared__ float sm[];
    float* sW   = sm + OFF_W;
    float* sImg = sm + OFF_IMG;
    float* sCap = sm + OFF_CAP;
    float* sSim = sm + OFF_SIM;
    float* sAttn= sm + OFF_ATTN;
    float* sAT  = sm + OFF_AT;
    float* sInv = sm + OFF_INVN;
    float* sRed = sm + OFF_RED;
    float* sB   = sm + OFF_B;

    const int i    = blockIdx.x;
    const int c    = blockIdx.y;
    const int tid  = threadIdx.x;
    const int w    = tid >> 5;
    const int lane = tid & 31;
    const int g    = w & 7;    // l-group: rows 5g..5g+4
    const int h    = w >> 3;   // d/s half

    const float* imgB = img_g + (size_t)i * (RN * DN);
    const float* capB = cap_g + (size_t)c * (LN * DN);

    if (tid < SN/4)
        *(float4*)(sB + tid*4) = *(const float4*)(b_g + tid*4);

    // ======== Phase 1: attn[r][l] = img[i,r,:] . cap[c,l,:] ========
    // 180 threads, each a 2r x 4l tile, float4 over d
    const int rg = tid / 10;          // 0..17 (tid<180)
    const int lg = tid - rg * 10;     // 0..9
    const int r0 = 2 * rg, l0 = 4 * lg;
    float p1[2][4];
    #pragma unroll
    for (int a = 0; a < 2; a++)
        #pragma unroll
        for (int b = 0; b < 4; b++) p1[a][b] = 0.f;

    for (int k = 0; k < NCH; k++) {
        __syncthreads();
        for (int idx = tid; idx < RN*(DC/4); idx += NT) {
            int r = idx >> 5, dq = idx & 31;
            *(float4*)(sImg + r*SP + dq*4) =
                *(const float4*)(imgB + r*DN + k*DC + dq*4);
        }
        for (int idx = tid; idx < LN*(DC/4); idx += NT) {
            int l = idx >> 5, dq = idx & 31;
            *(float4*)(sCap + l*SP + dq*4) =
                *(const float4*)(capB + l*DN + k*DC + dq*4);
        }
        __syncthreads();
        if (tid < 180) {
            #pragma unroll 2
            for (int d4 = 0; d4 < DC/4; d4++) {
                float4 av[2], cv[4];
                #pragma unroll
                for (int a = 0; a < 2; a++)
                    av[a] = *(float4*)(sImg + (r0+a)*SP + d4*4);
                #pragma unroll
                for (int b = 0; b < 4; b++)
                    cv[b] = *(float4*)(sCap + (l0+b)*SP + d4*4);
                #pragma unroll
                for (int a = 0; a < 2; a++)
                    #pragma unroll
                    for (int b = 0; b < 4; b++) {
                        p1[a][b] = fmaf(av[a].x, cv[b].x, p1[a][b]);
                        p1[a][b] = fmaf(av[a].y, cv[b].y, p1[a][b]);
                        p1[a][b] = fmaf(av[a].z, cv[b].z, p1[a][b]);
                        p1[a][b] = fmaf(av[a].w, cv[b].w, p1[a][b]);
                    }
            }
        }
    }
    __syncthreads();
    if (tid < 180) {
        #pragma unroll
        for (int a = 0; a < 2; a++)
            #pragma unroll
            for (int b = 0; b < 4; b++)
                sAttn[(r0+a)*41 + (l0+b)] = p1[a][b];
    }
    __syncthreads();

    // ======== Phase 2a: leaky relu + l2norm over l (per r) ========
    if (tid < RN) {
        float ss = 0.f;
        #pragma unroll 4
        for (int l = 0; l < LN; l++) {
            float x = sAttn[tid*41 + l];
            x = (x > 0.f) ? x : 0.1f * x;
            sAttn[tid*41 + l] = x;
            ss = fmaf(x, x, ss);
        }
        float inv = 1.f / (sqrtf(ss) + 1e-8f);
        #pragma unroll 4
        for (int l = 0; l < LN; l++) sAttn[tid*41 + l] *= inv;
    }
    __syncthreads();

    // ======== Phase 2b: softmax over r (per l) -> sAT[l][r] ========
    if (tid < LN) {
        float mx = -1e30f;
        #pragma unroll 4
        for (int r = 0; r < RN; r++)
            mx = fmaxf(mx, sAttn[r*41 + tid] * 9.0f);
        float sum = 0.f;
        #pragma unroll 4
        for (int r = 0; r < RN; r++) {
            float e = expf(sAttn[r*41 + tid] * 9.0f - mx);
            sAT[tid*40 + r] = e;
            sum += e;
        }
        float inv = 1.f / sum;
        #pragma unroll 4
        for (int r = 0; r < RN; r++) sAT[tid*40 + r] *= inv;
    }

    // ======== Phase 3a: wc sum-of-squares (pass 1 over D) ========
    // warp (g,h): l rows 5g..5g+4 ; lane owns d = h*64 + lane*2 (float2)
    const int dlo = h*64 + lane*2;
    float ssq[5] = {0.f,0.f,0.f,0.f,0.f};
    for (int k = 0; k < NCH; k++) {
        __syncthreads();
        for (int idx = tid; idx < RN*(DC/4); idx += NT) {
            int r = idx >> 5, dq = idx & 31;
            *(float4*)(sImg + r*SP + dq*4) =
                *(const float4*)(imgB + r*DN + k*DC + dq*4);
        }
        __syncthreads();
        float wcx[5], wcy[5];
        #pragma unroll
        for (int ii = 0; ii < 5; ii++) { wcx[ii]=0.f; wcy[ii]=0.f; }
        #pragma unroll 3
        for (int r = 0; r < RN; r += 4) {
            float2 im[4];
            #pragma unroll
            for (int q = 0; q < 4; q++)
                im[q] = *(float2*)(sImg + (r+q)*SP + dlo);
            #pragma unroll
            for (int ii = 0; ii < 5; ii++) {
                float4 a4 = *(float4*)(sAT + (5*g+ii)*40 + r);
                wcx[ii] = fmaf(a4.x, im[0].x, wcx[ii]);
                wcy[ii] = fmaf(a4.x, im[0].y, wcy[ii]);
                wcx[ii] = fmaf(a4.y, im[1].x, wcx[ii]);
                wcy[ii] = fmaf(a4.y, im[1].y, wcy[ii]);
                wcx[ii] = fmaf(a4.z, im[2].x, wcx[ii]);
                wcy[ii] = fmaf(a4.z, im[2].y, wcy[ii]);
                wcx[ii] = fmaf(a4.w, im[3].x, wcx[ii]);
                wcy[ii] = fmaf(a4.w, im[3].y, wcy[ii]);
            }
        }
        #pragma unroll
        for (int ii = 0; ii < 5; ii++)
            ssq[ii] += wcx[ii]*wcx[ii] + wcy[ii]*wcy[ii];
    }
    #pragma unroll
    for (int ii = 0; ii < 5; ii++) {
        float s = warp_sum(ssq[ii]);
        if (lane == 0) sRed[(5*g+ii)*2 + h] = s;
    }
    __syncthreads();
    if (tid < LN)
        sInv[tid] = 1.f / (sqrtf(sRed[tid*2] + sRed[tid*2+1]) + 1e-8f);

    // ======== Phase 3b: wc -> sim -> GEMM sim @ W ========
    // GEMM: warp (g,h): l = 5g+kk ; s = 128h + lane*4 .. +3
    const int s0 = h*128 + lane*4;
    float acc[5][4];
    #pragma unroll
    for (int kk = 0; kk < 5; kk++)
        #pragma unroll
        for (int j = 0; j < 4; j++) acc[kk][j] = 0.f;

    for (int k = 0; k < NCH; k++) {
        __syncthreads();
        for (int idx = tid; idx < RN*(DC/4); idx += NT) {
            int r = idx >> 5, dq = idx & 31;
            *(float4*)(sImg + r*SP + dq*4) =
                *(const float4*)(imgB + r*DN + k*DC + dq*4);
        }
        for (int idx = tid; idx < LN*(DC/4); idx += NT) {
            int l = idx >> 5, dq = idx & 31;
            *(float4*)(sCap + l*SP + dq*4) =
                *(const float4*)(capB + l*DN + k*DC + dq*4);
        }
        for (int idx = tid; idx < DC*(SN/4); idx += NT) {
            int d = idx >> 6, sq = idx & 63;
            *(float4*)(sW + d*SN + sq*4) =
                *(const float4*)(W_g + (size_t)(k*DC + d)*SN + sq*4);
        }
        __syncthreads();

        // wc recompute for this chunk
        float wcx[5], wcy[5];
        #pragma unroll
        for (int ii = 0; ii < 5; ii++) { wcx[ii]=0.f; wcy[ii]=0.f; }
        #pragma unroll 3
        for (int r = 0; r < RN; r += 4) {
            float2 im[4];
            #pragma unroll
            for (int q = 0; q < 4; q++)
                im[q] = *(float2*)(sImg + (r+q)*SP + dlo);
            #pragma unroll
            for (int ii = 0; ii < 5; ii++) {
                float4 a4 = *(float4*)(sAT + (5*g+ii)*40 + r);
                wcx[ii] = fmaf(a4.x, im[0].x, wcx[ii]);
                wcy[ii] = fmaf(a4.x, im[0].y, wcy[ii]);
                wcx[ii] = fmaf(a4.y, im[1].x, wcx[ii]);
                wcy[ii] = fmaf(a4.y, im[1].y, wcy[ii]);
                wcx[ii] = fmaf(a4.z, im[2].x, wcx[ii]);
                wcy[ii] = fmaf(a4.z, im[2].y, wcy[ii]);
                wcx[ii] = fmaf(a4.w, im[3].x, wcx[ii]);
                wcy[ii] = fmaf(a4.w, im[3].y, wcy[ii]);
            }
        }
        #pragma unroll
        for (int ii = 0; ii < 5; ii++) {
            float inv = sInv[5*g+ii];
            float2 cp = *(float2*)(sCap + (5*g+ii)*SP + dlo);
            float v0 = fmaf(wcx[ii], inv, -cp.x);
            float v1 = fmaf(wcy[ii], inv, -cp.y);
            float2 sv; sv.x = v0*v0; sv.y = v1*v1;
            *(float2*)(sSim + (5*g+ii)*SP + dlo) = sv;
        }
        __syncthreads();

        // GEMM over this chunk, 4 d at a time
        #pragma unroll 2
        for (int d = 0; d < DC; d += 4) {
            float4 sv[5];
            #pragma unroll
            for (int kk = 0; kk < 5; kk++)
                sv[kk] = *(float4*)(sSim + (5*g+kk)*SP + d);
            #pragma unroll
            for (int dd = 0; dd < 4; dd++) {
                float4 wv = *(float4*)(sW + (d+dd)*SN + s0);
                #pragma unroll
                for (int kk = 0; kk < 5; kk++) {
                    float s = (dd==0) ? sv[kk].x : (dd==1) ? sv[kk].y
                            : (dd==2) ? sv[kk].z : sv[kk].w;
                    acc[kk][0] = fmaf(s, wv.x, acc[kk][0]);
                    acc[kk][1] = fmaf(s, wv.y, acc[kk][1]);
                    acc[kk][2] = fmaf(s, wv.z, acc[kk][2]);
                    acc[kk][3] = fmaf(s, wv.w, acc[kk][3]);
                }
            }
        }
    }

    // ======== Epilogue: +b, relu, l2norm over s (split halves), mask ========
    const int clen = lens_g[c];
    float vs[5][4];
    #pragma unroll
    for (int kk = 0; kk < 5; kk++) {
        float pss = 0.f;
        #pragma unroll
        for (int j = 0; j < 4; j++) {
            float v = acc[kk][j] + sB[s0 + j];
            v = fmaxf(v, 0.f);
            vs[kk][j] = v;
            pss = fmaf(v, v, pss);
        }
        pss = warp_sum(pss);
        if (lane == 0) sRed[(5*g+kk)*2 + h] = pss;
    }
    __syncthreads();
    if (tid < LN) {
        float ss = sRed[tid*2] + sRed[tid*2+1];
        float inv = 1.f / (sqrtf(ss) + 1e-8f);
        sInv[tid] = (tid < clen) ? inv : 0.f;
    }
    __syncthreads();

    float* outB = out_g + (size_t)(c*IN_N + i) * (LN*SN);
    #pragma unroll
    for (int kk = 0; kk < 5; kk++) {
        const int l = 5*g + kk;
        float inv = sInv[l];
        float4 o;
        o.x = vs[kk][0]*inv; o.y = vs[kk][1]*inv;
        o.z = vs[kk][2]*inv; o.w = vs[kk][3]*inv;
        *(float4*)(outB + (size_t)l*SN + s0) = o;
    }
}

extern "C" void kernel_launch(void* const* d_in, const int* in_sizes, int n_in,
                              void* d_out, int out_size)
{
    const float* img  = (const float*)d_in[0];
    const float* cap  = (const float*)d_in[1];
    const int*   lens = (const int*)  d_in[2];
    const float* W    = (const float*)d_in[5];
    const float* b    = (const float*)d_in[6];
    float* out = (float*)d_out;
    (void)in_sizes; (void)n_in; (void)out_size;

    cudaFuncSetAttribute(graphembt_kernel,
                         cudaFuncAttributeMaxDynamicSharedMemorySize,
                         SMEM_FLOATS * sizeof(float));

    dim3 grid(IN_N, CN);
    graphembt_kernel<<<grid, NT, SMEM_FLOATS * sizeof(float)>>>(
        img, cap, lens, W, b, out);
}